// round 4
// baseline (speedup 1.0000x reference)
#include <cuda_runtime.h>
#include <cstdint>

// ============================================================================
// FlattenedObsEncoder: out[16384,1024] = (gather(W_embed,x)+b_embed) @ W_dense + b_dense
// tf32 mma.sync GEMM (base sm_103 target: tcgen05 is arch-'a'-only and the
// harness ptxas pass targets sm_103, so HMMA mma.sync is the tensor path).
// M=16384, N=1024, K=1024.  A is gathered on the fly (x is 1/4 the bytes of A).
// ============================================================================

#define B_SZ   16384
#define P_SZ   256            // W*H positions per batch row
#define K_SZ   1024           // EMBED * P_SZ
#define N_SZ   1024
#define MT     256            // M rows per CTA
#define NT     128            // N cols per CTA
#define KC     32             // K elements per chunk (8 positions * EMBED 4)
#define NCHUNK (K_SZ / KC)    // 32
#define THREADS 512
#define SA     36             // A smem row stride in floats (KC + 4 pad)
#define SB     36             // B smem row stride in floats
#define A_BUF  (MT * SA)      // 9216 floats
#define B_BUF  (NT * SB)      // 4608 floats
#define SMEM_BYTES ((2 * A_BUF + 2 * B_BUF) * 4)   // 110592 B

// W_dense transposed to [N][K], tf32-rounded (module-static, no runtime alloc).
__device__ float g_WdT[(size_t)N_SZ * K_SZ];

// ---------------------------------------------------------------------------
__device__ __forceinline__ uint32_t smem_u32(const void* p) {
    uint32_t a;
    asm("{ .reg .u64 t; cvta.to.shared.u64 t, %1; cvt.u32.u64 %0, t; }" : "=r"(a) : "l"(p));
    return a;
}
__device__ __forceinline__ float tf32_rn(float v) {
    float r;
    asm("cvt.rna.tf32.f32 %0, %1;" : "=f"(r) : "f"(v));
    return r;
}
__device__ __forceinline__ void cp16(uint32_t s, const void* g) {
    asm volatile("cp.async.cg.shared.global [%0], [%1], 16;" :: "r"(s), "l"(g));
}
#define CP_COMMIT() asm volatile("cp.async.commit_group;" ::: "memory")
#define CP_WAIT0()  asm volatile("cp.async.wait_group 0;" ::: "memory")

// ---------------------------------------------------------------------------
// Prepass: transpose W_dense [K,N] -> g_WdT [N,K], rounding to tf32.
// ---------------------------------------------------------------------------
__global__ void transpose_wd_kernel(const float* __restrict__ Wd) {
    __shared__ float t[32][33];
    const int tx = threadIdx.x, ty = threadIdx.y;
    const int n = blockIdx.x * 32 + tx;
    const int k = blockIdx.y * 32 + ty;
#pragma unroll
    for (int j = 0; j < 32; j += 8)
        t[ty + j][tx] = Wd[(size_t)(k + j) * N_SZ + n];
    __syncthreads();
    const int ko = blockIdx.y * 32 + tx;
    const int no = blockIdx.x * 32 + ty;
#pragma unroll
    for (int j = 0; j < 32; j += 8)
        g_WdT[(size_t)(no + j) * K_SZ + ko] = tf32_rn(t[tx][ty + j]);
}

// ---------------------------------------------------------------------------
// One m16n8k8 tf32 k-step for a 64(M)x32(N)... (warp tile 32x64):
// per warp: 2 m-tiles x 8 n-tiles.
// ---------------------------------------------------------------------------
__device__ __forceinline__ void compute_kstep(
    const float* __restrict__ As_, const float* __restrict__ Bs_,
    int warp_m, int warp_n, int g, int t4, int k0, float c[2][8][4]) {
    uint32_t a[2][4];
#pragma unroll
    for (int i = 0; i < 2; ++i) {
        const int r = warp_m * 32 + i * 16 + g;
        a[i][0] = __float_as_uint(As_[r * SA + k0 + t4]);
        a[i][1] = __float_as_uint(As_[(r + 8) * SA + k0 + t4]);
        a[i][2] = __float_as_uint(As_[r * SA + k0 + t4 + 4]);
        a[i][3] = __float_as_uint(As_[(r + 8) * SA + k0 + t4 + 4]);
    }
#pragma unroll
    for (int j = 0; j < 8; ++j) {
        const int nn = warp_n * 64 + j * 8 + g;
        const uint32_t b0 = __float_as_uint(Bs_[nn * SB + k0 + t4]);
        const uint32_t b1 = __float_as_uint(Bs_[nn * SB + k0 + t4 + 4]);
#pragma unroll
        for (int i = 0; i < 2; ++i) {
            asm volatile(
                "mma.sync.aligned.m16n8k8.row.col.f32.tf32.tf32.f32 "
                "{%0,%1,%2,%3}, {%4,%5,%6,%7}, {%8,%9}, {%0,%1,%2,%3};"
                : "+f"(c[i][j][0]), "+f"(c[i][j][1]),
                  "+f"(c[i][j][2]), "+f"(c[i][j][3])
                : "r"(a[i][0]), "r"(a[i][1]), "r"(a[i][2]), "r"(a[i][3]),
                  "r"(b0), "r"(b1));
        }
    }
}

// ---------------------------------------------------------------------------
// Main GEMM kernel.
// SMEM: As[2][MT][SA] | Bs[2][NT][SB]
// ---------------------------------------------------------------------------
__global__ void __launch_bounds__(THREADS, 1)
enc_gemm_kernel(const int* __restrict__ x, const float* __restrict__ We,
                const float* __restrict__ be, const float* __restrict__ bd,
                float* __restrict__ out) {
    extern __shared__ float smem[];
    float* Asm[2] = { smem, smem + A_BUF };
    float* Bsm[2] = { smem + 2 * A_BUF, smem + 2 * A_BUF + B_BUF };
    const uint32_t sbase = smem_u32(smem);
    const uint32_t aAddr[2] = { sbase, sbase + A_BUF * 4u };
    const uint32_t bAddr[2] = { sbase + 2u * A_BUF * 4u,
                                sbase + 2u * A_BUF * 4u + B_BUF * 4u };

    const int tid = threadIdx.x;
    const int wid = tid >> 5, lane = tid & 31;
    const int g = lane >> 2, t4 = lane & 3;
    const int warp_m = wid & 7;      // 8 x 32 rows = 256
    const int warp_n = wid >> 3;     // 2 x 64 cols = 128
    const int n0 = blockIdx.x * NT;
    const int m0 = blockIdx.y * MT;

    // --- A-build mapping: 2 threads per M row, 4 positions (16 floats) each
    const int arow = tid >> 1, ahalf = tid & 1;
    const int* xptr = x + (size_t)(m0 + arow) * P_SZ + ahalf * 4;
    const float4* We4 = (const float4*)We;
    const float be0 = be[0], be1 = be[1], be2 = be[2], be3 = be[3];
    const uint32_t aDstOff = (uint32_t)arow * (SA * 4u) + (uint32_t)ahalf * 64u;

    // --- B-copy mapping: 1024 16B chunks / 512 threads
    const float* bsrc = g_WdT + (size_t)n0 * K_SZ;

    float c[2][8][4];
#pragma unroll
    for (int i = 0; i < 2; ++i)
#pragma unroll
        for (int j = 0; j < 8; ++j)
#pragma unroll
            for (int q = 0; q < 4; ++q) c[i][j][q] = 0.0f;

    // ---- helper lambdas ----
    auto copyB = [&](int ch, int buf) {
#pragma unroll
        for (int i = 0; i < 2; ++i) {
            const int cc = tid + i * THREADS;
            const int row = cc >> 3, seg = cc & 7;
            cp16(bAddr[buf] + (uint32_t)row * (SB * 4u) + (uint32_t)seg * 16u,
                 bsrc + (size_t)row * K_SZ + ch * KC + seg * 4);
        }
    };
    auto stsA = [&](int buf, int p, float4 e) {
        const uint32_t vx = __float_as_uint(tf32_rn(e.x + be0));
        const uint32_t vy = __float_as_uint(tf32_rn(e.y + be1));
        const uint32_t vz = __float_as_uint(tf32_rn(e.z + be2));
        const uint32_t vw = __float_as_uint(tf32_rn(e.w + be3));
        asm volatile("st.shared.v4.b32 [%0], {%1,%2,%3,%4};"
                     :: "r"(aAddr[buf] + aDstOff + (uint32_t)p * 16u),
                        "r"(vx), "r"(vy), "r"(vz), "r"(vw) : "memory");
    };

    // ---- prologue: A(0) + B(0) into buf 0 ----
    {
        const int4 xi = *(const int4*)xptr;
        stsA(0, 0, __ldg(We4 + xi.x));
        stsA(0, 1, __ldg(We4 + xi.y));
        stsA(0, 2, __ldg(We4 + xi.z));
        stsA(0, 3, __ldg(We4 + xi.w));
        copyB(0, 0);
        CP_COMMIT();
    }

    // ---- mainloop ----
    for (int ch = 0; ch < NCHUNK; ++ch) {
        const int cur = ch & 1, nxt = cur ^ 1;
        const bool has_next = (ch + 1 < NCHUNK);

        CP_WAIT0();
        __syncthreads();          // A(ch) sts visible, B(ch) landed

        if (has_next) { copyB(ch + 1, nxt); CP_COMMIT(); }

        int4 xi = {0, 0, 0, 0};
        if (has_next) xi = *(const int4*)(xptr + (ch + 1) * 8);

        compute_kstep(Asm[cur], Bsm[cur], warp_m, warp_n, g, t4, 0,  c);
        compute_kstep(Asm[cur], Bsm[cur], warp_m, warp_n, g, t4, 8,  c);

        float4 e0, e1, e2, e3;
        if (has_next) {
            e0 = __ldg(We4 + xi.x);
            e1 = __ldg(We4 + xi.y);
            e2 = __ldg(We4 + xi.z);
            e3 = __ldg(We4 + xi.w);
        }

        compute_kstep(Asm[cur], Bsm[cur], warp_m, warp_n, g, t4, 16, c);
        compute_kstep(Asm[cur], Bsm[cur], warp_m, warp_n, g, t4, 24, c);

        if (has_next) {
            stsA(nxt, 0, e0); stsA(nxt, 1, e1);
            stsA(nxt, 2, e2); stsA(nxt, 3, e3);
        }
    }

    // ---- epilogue: accum + b_dense -> out ----
#pragma unroll
    for (int i = 0; i < 2; ++i) {
        const size_t r0 = (size_t)(m0 + warp_m * 32 + i * 16 + g);
#pragma unroll
        for (int j = 0; j < 8; ++j) {
            const int col = n0 + warp_n * 64 + j * 8 + t4 * 2;
            const float2 bb = *(const float2*)(bd + col);
            float2 v0, v1;
            v0.x = c[i][j][0] + bb.x;  v0.y = c[i][j][1] + bb.y;
            v1.x = c[i][j][2] + bb.x;  v1.y = c[i][j][3] + bb.y;
            *(float2*)(out + r0 * N_SZ + col)       = v0;
            *(float2*)(out + (r0 + 8) * N_SZ + col) = v1;
        }
    }
}

// ---------------------------------------------------------------------------
// kernel_launch
// ---------------------------------------------------------------------------
extern "C" void kernel_launch(void* const* d_in, const int* in_sizes, int n_in,
                              void* d_out, int out_size) {
    const int*   x  = (const int*)d_in[0];
    const float* We = (const float*)d_in[1];
    const float* be = (const float*)d_in[2];
    const float* Wd = (const float*)d_in[3];
    const float* bd = (const float*)d_in[4];
    float* out = (float*)d_out;

    // Opt into >48KB dynamic smem.  Only when NOT capturing: the harness runs
    // kernel_launch once uncaptured for correctness first, so the attribute is
    // already set before the capture call.
    cudaStreamCaptureStatus cs = cudaStreamCaptureStatusNone;
    cudaError_t qerr = cudaStreamIsCapturing((cudaStream_t)0, &cs);
    const bool capturing = (qerr != cudaSuccess) || (cs != cudaStreamCaptureStatusNone);
    if (!capturing) {
        cudaFuncSetAttribute(enc_gemm_kernel,
                             cudaFuncAttributeMaxDynamicSharedMemorySize, SMEM_BYTES);
    }
    (void)cudaGetLastError();

    transpose_wd_kernel<<<dim3(N_SZ / 32, K_SZ / 32), dim3(32, 8)>>>(Wd);
    enc_gemm_kernel<<<dim3(N_SZ / NT, B_SZ / MT), THREADS, SMEM_BYTES>>>(x, We, be, bd, out);
}